// round 11
// baseline (speedup 1.0000x reference)
#include <cuda_runtime.h>
#include <cstdint>

// FeatureDictionary — fused 8:1 block-specialized kernel (R10) +
// lane-split scalar loads in the gather path: smpl_F's 3 loads (12 random-line
// wavefronts/warp) and weights' 3 loads collapse to 2 predicated loads
// (~6 wavefronts) + 6 width-8 shuffles.
//  0 coords [B,S,3] f32   1 idx [B] i32         2 smpl_F [13776,3] i32
//  3 fid [B,S] i32        4 weights [B,S,3] f32  5 sdf [B,S,1] f32
//  6 hitpt [B,S,3] f32    7 codebooks [256,6890,64] f32
// Output: concat( weighted_feats [B,S,64], coords_feats [B,S,3], normal [B,S,3] )

#define NUM_VERTICES 6890
#define DFEAT 64

__global__ __launch_bounds__(256)
void fused_kernel(const float* __restrict__ coords,
                  const int*   __restrict__ idx,
                  const int*   __restrict__ smpl_F,
                  const int*   __restrict__ fid,
                  const float* __restrict__ weights,
                  const float* __restrict__ sdf,
                  const float* __restrict__ hitpt,
                  const float* __restrict__ codebooks,
                  float*       __restrict__ out,
                  int BS, int S, int Sshift)
{
    // Block-type decode: every 9th block (r==8) is a tail block.
    int blk = blockIdx.x;
    int q   = blk / 9;
    int r   = blk - q * 9;

    if (r == 8) {
        // ---- tail path: 1 thread per point, coalesced streaming ----
        int p = q * 256 + threadIdx.x;
        if (p >= BS) return;

        size_t C_OFF = (size_t)BS * DFEAT;
        size_t N_OFF = C_OFF + (size_t)BS * 3;

        float cx = __ldcs(coords + 3 * p + 0);
        float cy = __ldcs(coords + 3 * p + 1);
        float cz = __ldcs(coords + 3 * p + 2);
        float hx = __ldcs(hitpt  + 3 * p + 0);
        float hy = __ldcs(hitpt  + 3 * p + 1);
        float hz = __ldcs(hitpt  + 3 * p + 2);
        float w1 = __ldcs(weights + 3 * p + 1);
        float w2 = __ldcs(weights + 3 * p + 2);
        float sd = __ldcs(sdf + p);

        float dx = hx - cx, dy = hy - cy, dz = hz - cz;
        float nrm = sqrtf(dx * dx + dy * dy + dz * dz);
        float inv = 1.0f / fmaxf(nrm, 1e-6f);

        __stcs(out + N_OFF + 3 * (size_t)p + 0, dx * inv);
        __stcs(out + N_OFF + 3 * (size_t)p + 1, dy * inv);
        __stcs(out + N_OFF + 3 * (size_t)p + 2, dz * inv);
        __stcs(out + C_OFF + 3 * (size_t)p + 0, w1);
        __stcs(out + C_OFF + 3 * (size_t)p + 1, w2);
        __stcs(out + C_OFF + 3 * (size_t)p + 2, sd);
        return;
    }

    // ---- gather path: 8 lanes per point ----
    int gblk = q * 8 + r;
    int L    = gblk * 256 + threadIdx.x;
    int p    = L >> 3;
    int lane = L & 7;
    if (p >= BS) return;

    unsigned mask = __activemask();   // gather blocks are fully active

    int b = (Sshift >= 0) ? (p >> Sshift) : (p / S);
    int subj = __ldg(idx + b);
    const float* cb = codebooks + (size_t)subj * (NUM_VERTICES * DFEAT);

    int f = __ldcs(fid + p);

    // Lane-split scalar loads (one line-visit per point instead of three):
    //   lanes 0-2: smpl_F[3f+lane]   lanes 3-5: weights[3p+lane-3]
    int   rawV = 0;
    float rawW = 0.0f;
    if (lane < 3) rawV = __ldg(smpl_F + 3 * f + lane);
    if (lane >= 3 && lane < 6) rawW = __ldcs(weights + 3 * p + (lane - 3));

    int v0 = __shfl_sync(mask, rawV, 0, 8);
    int v1 = __shfl_sync(mask, rawV, 1, 8);
    int v2 = __shfl_sync(mask, rawV, 2, 8);
    float w0 = __shfl_sync(mask, rawW, 3, 8);
    float w1 = __shfl_sync(mask, rawW, 4, 8);
    float w2 = __shfl_sync(mask, rawW, 5, 8);

    const float4* r0 = (const float4*)(cb + (size_t)v0 * DFEAT);
    const float4* r1 = (const float4*)(cb + (size_t)v1 * DFEAT);
    const float4* r2 = (const float4*)(cb + (size_t)v2 * DFEAT);

    // 6 independent 128B-line loads in flight.
    float4 a0 = __ldg(r0 + lane);
    float4 c0 = __ldg(r1 + lane);
    float4 d0 = __ldg(r2 + lane);
    float4 a1 = __ldg(r0 + lane + 8);
    float4 c1 = __ldg(r1 + lane + 8);
    float4 d1 = __ldg(r2 + lane + 8);

    float4 o0, o1;
    o0.x = w0 * a0.x + w1 * c0.x + w2 * d0.x;
    o0.y = w0 * a0.y + w1 * c0.y + w2 * d0.y;
    o0.z = w0 * a0.z + w1 * c0.z + w2 * d0.z;
    o0.w = w0 * a0.w + w1 * c0.w + w2 * d0.w;
    o1.x = w0 * a1.x + w1 * c1.x + w2 * d1.x;
    o1.y = w0 * a1.y + w1 * c1.y + w2 * d1.y;
    o1.z = w0 * a1.z + w1 * c1.z + w2 * d1.z;
    o1.w = w0 * a1.w + w1 * c1.w + w2 * d1.w;

    float4* outv = (float4*)out + (size_t)p * (DFEAT / 4);
    __stcs(outv + lane,     o0);
    __stcs(outv + lane + 8, o1);
}

extern "C" void kernel_launch(void* const* d_in, const int* in_sizes, int n_in,
                              void* d_out, int out_size)
{
    const float* coords    = (const float*)d_in[0];
    const int*   idx       = (const int*)  d_in[1];
    const int*   smpl_F    = (const int*)  d_in[2];
    const int*   fid       = (const int*)  d_in[3];
    const float* weights   = (const float*)d_in[4];
    const float* sdf       = (const float*)d_in[5];
    const float* hitpt     = (const float*)d_in[6];
    const float* codebooks = (const float*)d_in[7];
    float*       out       = (float*)d_out;

    int BS = in_sizes[3];       // B*S
    int B  = in_sizes[1];       // batch
    int S  = BS / B;

    int Sshift = -1;
    if ((S & (S - 1)) == 0) {
        Sshift = 0;
        while ((1 << Sshift) < S) Sshift++;
    }

    int NB = (BS + 255) / 256;
    long long NA = ((long long)BS * 8 + 255) / 256;
    long long total = NA + NB;

    fused_kernel<<<(unsigned)total, 256>>>(
        coords, idx, smpl_F, fid, weights, sdf, hitpt, codebooks,
        out, BS, S, Sshift);
}

// round 12
// speedup vs baseline: 1.4448x; 1.4448x over previous
#include <cuda_runtime.h>
#include <cstdint>

// FeatureDictionary — R10 fused 8:1 kernel + face-vertex int4 table prepass.
// Prepass expands smpl_F [13776,3] into padded int4 table (16B-aligned) so the
// gather path does ONE aligned int4 load per point (4 wavefronts/warp) instead
// of three scalar loads (12 wavefronts/warp), and shortens the index chain.
//  0 coords [B,S,3] f32   1 idx [B] i32         2 smpl_F [13776,3] i32
//  3 fid [B,S] i32        4 weights [B,S,3] f32  5 sdf [B,S,1] f32
//  6 hitpt [B,S,3] f32    7 codebooks [256,6890,64] f32
// Output: concat( weighted_feats [B,S,64], coords_feats [B,S,3], normal [B,S,3] )

#define NUM_VERTICES 6890
#define NUM_FACES_MAX 16384
#define DFEAT 64

__device__ int4 g_faceVerts[NUM_FACES_MAX];   // 256KB scratch (allowed)

__global__ __launch_bounds__(256)
void face_table_kernel(const int* __restrict__ smpl_F, int nFaces)
{
    int t = blockIdx.x * blockDim.x + threadIdx.x;
    if (t >= nFaces) return;
    int v0 = __ldg(smpl_F + 3 * t + 0);
    int v1 = __ldg(smpl_F + 3 * t + 1);
    int v2 = __ldg(smpl_F + 3 * t + 2);
    g_faceVerts[t] = make_int4(v0, v1, v2, 0);
}

__global__ __launch_bounds__(256, 8)
void fused_kernel(const float* __restrict__ coords,
                  const int*   __restrict__ idx,
                  const int*   __restrict__ fid,
                  const float* __restrict__ weights,
                  const float* __restrict__ sdf,
                  const float* __restrict__ hitpt,
                  const float* __restrict__ codebooks,
                  float*       __restrict__ out,
                  int BS, int S, int Sshift)
{
    // Block-type decode: every 9th block (r==8) is a tail block.
    int blk = blockIdx.x;
    int q   = blk / 9;
    int r   = blk - q * 9;

    if (r == 8) {
        // ---- tail path: 1 thread per point, coalesced streaming ----
        int p = q * 256 + threadIdx.x;
        if (p >= BS) return;

        size_t C_OFF = (size_t)BS * DFEAT;
        size_t N_OFF = C_OFF + (size_t)BS * 3;

        float cx = __ldcs(coords + 3 * p + 0);
        float cy = __ldcs(coords + 3 * p + 1);
        float cz = __ldcs(coords + 3 * p + 2);
        float hx = __ldcs(hitpt  + 3 * p + 0);
        float hy = __ldcs(hitpt  + 3 * p + 1);
        float hz = __ldcs(hitpt  + 3 * p + 2);
        float w1 = __ldcs(weights + 3 * p + 1);
        float w2 = __ldcs(weights + 3 * p + 2);
        float sd = __ldcs(sdf + p);

        float dx = hx - cx, dy = hy - cy, dz = hz - cz;
        float nrm = sqrtf(dx * dx + dy * dy + dz * dz);
        float inv = 1.0f / fmaxf(nrm, 1e-6f);

        __stcs(out + N_OFF + 3 * (size_t)p + 0, dx * inv);
        __stcs(out + N_OFF + 3 * (size_t)p + 1, dy * inv);
        __stcs(out + N_OFF + 3 * (size_t)p + 2, dz * inv);
        __stcs(out + C_OFF + 3 * (size_t)p + 0, w1);
        __stcs(out + C_OFF + 3 * (size_t)p + 1, w2);
        __stcs(out + C_OFF + 3 * (size_t)p + 2, sd);
        return;
    }

    // ---- gather path: 8 lanes per point ----
    int gblk = q * 8 + r;
    int L    = gblk * 256 + threadIdx.x;
    int p    = L >> 3;
    int lane = L & 7;
    if (p >= BS) return;

    int b = (Sshift >= 0) ? (p >> Sshift) : (p / S);
    int subj = __ldg(idx + b);
    const float* cb = codebooks + (size_t)subj * (NUM_VERTICES * DFEAT);

    int f = __ldcs(fid + p);
    int4 v = __ldg(&g_faceVerts[f]);   // one aligned 16B load: v0,v1,v2

    float w0 = __ldcs(weights + 3 * p + 0);
    float w1 = __ldcs(weights + 3 * p + 1);
    float w2 = __ldcs(weights + 3 * p + 2);

    const float4* r0 = (const float4*)(cb + (size_t)v.x * DFEAT);
    const float4* r1 = (const float4*)(cb + (size_t)v.y * DFEAT);
    const float4* r2 = (const float4*)(cb + (size_t)v.z * DFEAT);

    // 6 independent 128B-line loads in flight.
    float4 a0 = __ldg(r0 + lane);
    float4 c0 = __ldg(r1 + lane);
    float4 d0 = __ldg(r2 + lane);
    float4 a1 = __ldg(r0 + lane + 8);
    float4 c1 = __ldg(r1 + lane + 8);
    float4 d1 = __ldg(r2 + lane + 8);

    float4 o0, o1;
    o0.x = w0 * a0.x + w1 * c0.x + w2 * d0.x;
    o0.y = w0 * a0.y + w1 * c0.y + w2 * d0.y;
    o0.z = w0 * a0.z + w1 * c0.z + w2 * d0.z;
    o0.w = w0 * a0.w + w1 * c0.w + w2 * d0.w;
    o1.x = w0 * a1.x + w1 * c1.x + w2 * d1.x;
    o1.y = w0 * a1.y + w1 * c1.y + w2 * d1.y;
    o1.z = w0 * a1.z + w1 * c1.z + w2 * d1.z;
    o1.w = w0 * a1.w + w1 * c1.w + w2 * d1.w;

    float4* outv = (float4*)out + (size_t)p * (DFEAT / 4);
    __stcs(outv + lane,     o0);
    __stcs(outv + lane + 8, o1);
}

extern "C" void kernel_launch(void* const* d_in, const int* in_sizes, int n_in,
                              void* d_out, int out_size)
{
    const float* coords    = (const float*)d_in[0];
    const int*   idx       = (const int*)  d_in[1];
    const int*   smpl_F    = (const int*)  d_in[2];
    const int*   fid       = (const int*)  d_in[3];
    const float* weights   = (const float*)d_in[4];
    const float* sdf       = (const float*)d_in[5];
    const float* hitpt     = (const float*)d_in[6];
    const float* codebooks = (const float*)d_in[7];
    float*       out       = (float*)d_out;

    int BS = in_sizes[3];       // B*S
    int B  = in_sizes[1];       // batch
    int S  = BS / B;
    int nFaces = in_sizes[2] / 3;

    int Sshift = -1;
    if ((S & (S - 1)) == 0) {
        Sshift = 0;
        while ((1 << Sshift) < S) Sshift++;
    }

    // Prepass: build padded int4 face-vertex table (tiny, ~2-3us).
    face_table_kernel<<<(nFaces + 255) / 256, 256>>>(smpl_F, nFaces);

    int NB = (BS + 255) / 256;
    long long NA = ((long long)BS * 8 + 255) / 256;
    long long total = NA + NB;

    fused_kernel<<<(unsigned)total, 256>>>(
        coords, idx, fid, weights, sdf, hitpt, codebooks,
        out, BS, S, Sshift);
}